// round 14
// baseline (speedup 1.0000x reference)
#include <cuda_runtime.h>
#include <math.h>

// Fused MSE + SSIM loss:  out = mean((p-t)^2) + 1 - mean(S)
// 11-tap separable gaussian (sigma=1.5, R=5), edge padding.
// Sum/difference basis: smem holds sd=(p+t, p-t) pairs.
//   conv(s)=ux+uy=US, conv(d)=ux-uy=UD, conv(s^2)=US2, conv(d^2)=UD2
//   2uxuy=(US^2-UD^2)/2, ux^2+uy^2=(US^2+UD^2)/2,
//   uxx+uyy=(US2+UD2)/2, uxy=(US2-UD2)/4
// Packed f32x2 fma; h-fields as ulonglong2{(US,UD),(US2,UD2)} per point.
// 32x64 tiles, 8-out h-windows, 8-row v-groups, last-block finalize.

#define RW    5
#define TW    32              // tile width
#define TH    64              // tile height
#define HW    (TW + 2*RW)     // 42
#define HH    (TH + 2*RW)     // 74
#define HST2  46              // sd row stride in float2 (368B, 92 words % 32 = 28)
#define CSTE  33              // hAB row stride in ulonglong2 (528B, 132 words % 32 = 4)
#define IMG   512

#define SPT_BYTES  (HH * HST2 * 8)              // 27232
#define HAB_BYTES  (HH * CSTE * 16)             // 39072
#define SMEM_BYTES (SPT_BYTES + HAB_BYTES)      // 66304

// normalized gaussian weights, sigma=1.5, t=-5..5 (f64-computed, cast f32)
#define KW0 0.00102838f
#define KW1 0.00759876f
#define KW2 0.03600076f
#define KW3 0.10936070f
#define KW4 0.21300554f
#define KW5 0.26601172f

__device__ double g_acc[2];        // [0]=sum(S), [1]=sum((p-t)^2)
__device__ unsigned int g_count;   // blocks-done counter

typedef unsigned long long u64;

// ---- f32x2 helpers (u64 carrier, "l" constraint) ----
__device__ __forceinline__ u64 pack2(float lo, float hi) {
    u64 d;
    asm("mov.b64 %0, {%1, %2};" : "=l"(d) : "f"(lo), "f"(hi));
    return d;
}
__device__ __forceinline__ void unpack2(u64 v, float& lo, float& hi) {
    asm("mov.b64 {%0, %1}, %2;" : "=f"(lo), "=f"(hi) : "l"(v));
}
__device__ __forceinline__ void fma2(u64& acc, u64 a, u64 b) {
    asm("fma.rn.f32x2 %0, %1, %2, %0;" : "+l"(acc) : "l"(a), "l"(b));
}
__device__ __forceinline__ u64 mul2(u64 a, u64 b) {
    u64 r;
    asm("mul.rn.f32x2 %0, %1, %2;" : "=l"(r) : "l"(a), "l"(b));
    return r;
}

__global__ __launch_bounds__(256, 3) void ssim_mse_kernel(
    const float* __restrict__ pred, const float* __restrict__ targ,
    float* __restrict__ out, double inv_n, unsigned int total_blocks)
{
    extern __shared__ __align__(16) char smem_raw[];
    float2     (*sd)[HST2]  = (float2(*)[HST2])smem_raw;              // (s, d)
    ulonglong2 (*hAB)[CSTE] = (ulonglong2(*)[CSTE])(smem_raw + SPT_BYTES); // {(US,UD),(US2,UD2)}
    __shared__ float rs[8], rm[8];

    const float C1f = 0.0004f;
    const float C2f = 0.0036f;

    const int tid = threadIdx.x;
    const int bx = blockIdx.x * TW;
    const int by = blockIdx.y * TH;
    const size_t base = (size_t)blockIdx.z * (IMG * IMG);
    const float* __restrict__ P = pred + base;
    const float* __restrict__ T = targ + base;

    // weight pairs (w,w); kernel symmetric -> 6 distinct
    u64 wp[6];
    wp[0] = pack2(KW0, KW0); wp[1] = pack2(KW1, KW1); wp[2] = pack2(KW2, KW2);
    wp[3] = pack2(KW3, KW3); wp[4] = pack2(KW4, KW4); wp[5] = pack2(KW5, KW5);

    float m_sum = 0.f;

    // ---- load halo: compute (s,d) once per point; MSE on interior ----
    #pragma unroll 4
    for (int idx = tid; idx < HH * HW; idx += 256) {
        int r = idx / HW;
        int c = idx - r * HW;
        int gy = min(max(by + r - RW, 0), IMG - 1);
        int gx = min(max(bx + c - RW, 0), IMG - 1);
        int g = gy * IMG + gx;
        float p = P[g], t = T[g];
        float sv = p + t, dv = p - t;
        sd[r][c] = make_float2(sv, dv);
        if (r >= RW && r < RW + TH && c >= RW && c < RW + TW) {
            m_sum = fmaf(dv, dv, m_sum);
        }
    }
    __syncthreads();

    // ---- horizontal pass: HH rows x 4 groups of 8 outputs ----
    // unit u: row = u % HH, cg = u / HH  (warp = 32 consecutive rows, same cg)
    #pragma unroll 1
    for (int u = tid; u < HH * 4; u += 256) {
        int row = u % HH;
        int cg  = u / HH;
        int c0  = cg * 8;

        u64 a01[8], a23[8];
        #pragma unroll
        for (int oc = 0; oc < 8; oc++) { a01[oc] = 0ULL; a23[oc] = 0ULL; }

        #pragma unroll
        for (int i = 0; i < 9; i++) {
            ulonglong2 v = *(const ulonglong2*)&sd[row][c0 + 2 * i];
            #pragma unroll
            for (int half = 0; half < 2; half++) {
                int j = 2 * i + half;
                u64 sdj = half ? v.y : v.x;
                u64 s2d2 = mul2(sdj, sdj);
                #pragma unroll
                for (int oc = 0; oc < 8; oc++) {
                    int k = j - oc;
                    if (k >= 0 && k <= 10) {
                        int kk = (k <= 5) ? k : 10 - k;
                        fma2(a01[oc], wp[kk], sdj);
                        fma2(a23[oc], wp[kk], s2d2);
                    }
                }
            }
        }
        #pragma unroll
        for (int oc = 0; oc < 8; oc++)
            hAB[row][c0 + oc] = make_ulonglong2(a01[oc], a23[oc]);
    }
    __syncthreads();

    // ---- vertical pass: 32 cols x 8 groups of 8 rows ----
    const int tx = tid & 31;
    const int r0 = (tid >> 5) * 8;

    u64 aA[8], aB[8];
    #pragma unroll
    for (int i = 0; i < 8; i++) { aA[i] = 0ULL; aB[i] = 0ULL; }

    #pragma unroll
    for (int j = 0; j < 18; j++) {
        ulonglong2 f = hAB[r0 + j][tx];
        #pragma unroll
        for (int orow = 0; orow < 8; orow++) {
            int k = j - orow;
            if (k >= 0 && k <= 10) {
                int kk = (k <= 5) ? k : 10 - k;
                fma2(aA[orow], wp[kk], f.x);
                fma2(aB[orow], wp[kk], f.y);
            }
        }
    }

    float s_sum = 0.f;
    #pragma unroll
    for (int orow = 0; orow < 8; orow++) {
        float US, UD, US2, UD2;
        unpack2(aA[orow], US, UD);
        unpack2(aB[orow], US2, UD2);
        float Pq = US * US;
        float Qq = UD * UD;
        float e1 = (Pq - Qq) * 0.5f;                 // 2*ux*uy
        float e3 = (Pq + Qq) * 0.5f;                 // ux^2 + uy^2
        float e2 = (US2 - UD2) * 0.5f - e1;          // 2*vxy
        float e4 = (US2 + UD2) * 0.5f - e3;          // vx + vy
        float num = (e1 + C1f) * (e2 + C2f);
        float den = (e3 + C1f) * (e4 + C2f);
        s_sum += __fdividef(num, den);
    }

    // ---- block reduction ----
    #pragma unroll
    for (int o = 16; o > 0; o >>= 1) {
        s_sum += __shfl_down_sync(0xFFFFFFFFu, s_sum, o);
        m_sum += __shfl_down_sync(0xFFFFFFFFu, m_sum, o);
    }
    const int wy = tid >> 5;
    if (tx == 0) { rs[wy] = s_sum; rm[wy] = m_sum; }
    __syncthreads();

    if (tid == 0) {
        float S = 0.f, M = 0.f;
        #pragma unroll
        for (int i = 0; i < 8; i++) { S += rs[i]; M += rm[i]; }
        atomicAdd(&g_acc[0], (double)S);
        atomicAdd(&g_acc[1], (double)M);
        __threadfence();
        unsigned int done = atomicAdd(&g_count, 1u);
        if (done == total_blocks - 1u) {
            // last block: finalize + reset for next graph replay
            double Sg = g_acc[0];
            double Mg = g_acc[1];
            out[0] = (float)(Mg * inv_n + 1.0 - Sg * inv_n);
            g_acc[0] = 0.0;
            g_acc[1] = 0.0;
            g_count = 0u;
            __threadfence();
        }
    }
}

extern "C" void kernel_launch(void* const* d_in, const int* in_sizes, int n_in,
                              void* d_out, int out_size)
{
    const float* pred = (const float*)d_in[0];
    const float* targ = (const float*)d_in[1];
    float* out = (float*)d_out;

    const int n_total = in_sizes[0];
    const int channels = n_total / (IMG * IMG);

    static int attr_set = 0;
    if (!attr_set) {
        cudaFuncSetAttribute(ssim_mse_kernel,
                             cudaFuncAttributeMaxDynamicSharedMemorySize,
                             SMEM_BYTES);
        attr_set = 1;
    }

    dim3 grid(IMG / TW, IMG / TH, channels);
    unsigned int total_blocks = grid.x * grid.y * grid.z;
    ssim_mse_kernel<<<grid, 256, SMEM_BYTES>>>(pred, targ, out,
                                               1.0 / (double)n_total,
                                               total_blocks);
}